// round 7
// baseline (speedup 1.0000x reference)
#include <cuda_runtime.h>
#include <cuda_bf16.h>
#include <cstdint>

#define NN 64
#define CC 256
#define TT 64
#define VV 25
#define VP2 26                  // padded v
#define TVP (TT * VP2)          // 1664 padded columns
#define NJ 104                  // columns per CTA tile (4 v-groups)
#define ELEMS26 (NN * CC * TVP)

typedef unsigned long long ull;

// Device scratch (no cudaMalloc allowed) — activations as bf16 hi/lo, padded-26
__device__ __nv_bfloat16 g_xh0[ELEMS26];
__device__ __nv_bfloat16 g_xl0[ELEMS26];
__device__ __nv_bfloat16 g_xh1[ELEMS26];
__device__ __nv_bfloat16 g_xl1[ELEMS26];
__device__ __nv_bfloat16 g_whi[4 * CC * CC];
__device__ __nv_bfloat16 g_wlo[4 * CC * CC];

// ---------------- PTX helpers ----------------
__device__ __forceinline__ uint32_t smem_u32(const void* p) {
    uint32_t a;
    asm("{ .reg .u64 t; cvta.to.shared.u64 t, %1; cvt.u32.u64 %0, t; }" : "=r"(a) : "l"(p));
    return a;
}
__device__ __forceinline__ ull ffma2(ull a, ull b, ull c) {
    ull d; asm("fma.rn.f32x2 %0, %1, %2, %3;" : "=l"(d) : "l"(a), "l"(b), "l"(c)); return d;
}
__device__ __forceinline__ ull pack2(float x) {
    ull d; unsigned xu = __float_as_uint(x);
    asm("mov.b64 %0, {%1, %2};" : "=l"(d) : "r"(xu), "r"(xu)); return d;
}
__device__ __forceinline__ ull pack2f(float lo, float hi) {
    ull d; asm("mov.b64 %0, {%1, %2};" : "=l"(d) : "r"(__float_as_uint(lo)), "r"(__float_as_uint(hi))); return d;
}
__device__ __forceinline__ float lo32(ull a) { return __uint_as_float((unsigned)(a & 0xffffffffULL)); }
__device__ __forceinline__ float hi32(ull a) { return __uint_as_float((unsigned)(a >> 32)); }

__device__ __forceinline__ void ldsm_x4(uint32_t* r, uint32_t addr) {
    asm volatile("ldmatrix.sync.aligned.m8n8.x4.shared.b16 {%0,%1,%2,%3}, [%4];"
                 : "=r"(r[0]), "=r"(r[1]), "=r"(r[2]), "=r"(r[3]) : "r"(addr));
}
__device__ __forceinline__ void ldsm_x4_t(uint32_t* r, uint32_t addr) {
    asm volatile("ldmatrix.sync.aligned.m8n8.x4.trans.shared.b16 {%0,%1,%2,%3}, [%4];"
                 : "=r"(r[0]), "=r"(r[1]), "=r"(r[2]), "=r"(r[3]) : "r"(addr));
}
__device__ __forceinline__ void mma_bf16(float* c, const uint32_t* a, const uint32_t* b) {
    asm volatile("mma.sync.aligned.m16n8k16.row.col.f32.bf16.bf16.f32 "
                 "{%0,%1,%2,%3}, {%4,%5,%6,%7}, {%8,%9}, {%0,%1,%2,%3};"
                 : "+f"(c[0]), "+f"(c[1]), "+f"(c[2]), "+f"(c[3])
                 : "r"(a[0]), "r"(a[1]), "r"(a[2]), "r"(a[3]), "r"(b[0]), "r"(b[1]));
}
__device__ __forceinline__ void cp16(uint32_t dst, const void* src) {
    asm volatile("cp.async.cg.shared.global [%0], [%1], 16;" :: "r"(dst), "l"(src) : "memory");
}
#define CP_COMMIT() asm volatile("cp.async.commit_group;" ::: "memory")

__device__ __forceinline__ uint32_t bsplit2(float v0, float v1,
                                            float& l0f, float& l1f) {
    __nv_bfloat162 hh;
    hh.x = __float2bfloat16_rn(v0);
    hh.y = __float2bfloat16_rn(v1);
    l0f = v0 - __bfloat162float(hh.x);
    l1f = v1 - __bfloat162float(hh.y);
    return *(uint32_t*)&hh;
}

// ---------------- W split (once, all 4 layers) ----------------
__global__ void __launch_bounds__(256)
wsplit_kernel(const float* __restrict__ w0, const float* __restrict__ w1,
              const float* __restrict__ w2, const float* __restrict__ w3,
              __nv_bfloat16* __restrict__ whi, __nv_bfloat16* __restrict__ wlo)
{
    int id = blockIdx.x * 256 + threadIdx.x;
    const float* ws[4] = { w0, w1, w2, w3 };
    float v = ws[id >> 16][id & 65535];
    __nv_bfloat16 h = __float2bfloat16_rn(v);
    whi[id] = h;
    wlo[id] = __float2bfloat16_rn(v - __bfloat162float(h));
}

// ---------------- X split: dense fp32 [.,25] -> padded bf16 hi/lo [.,26] ----------------
// CTA handles 256 rows (4 contiguous (n,c) slabs).
__global__ void __launch_bounds__(256)
xsplit_kernel(const float* __restrict__ in,
              __nv_bfloat16* __restrict__ xh, __nv_bfloat16* __restrict__ xl)
{
    __shared__ float slab[6400];
    const int tid = threadIdx.x;
    const size_t ibase = (size_t)blockIdx.x * 6400;
    const size_t obase = (size_t)blockIdx.x * 256 * VP2;
    for (int i = tid; i < 6400; i += 256) slab[i] = in[ibase + i];
    __syncthreads();

    const float* z = slab + tid * 25;
    uint32_t* oh = (uint32_t*)(xh + obase + tid * VP2);
    uint32_t* ol = (uint32_t*)(xl + obase + tid * VP2);
#pragma unroll
    for (int j = 0; j < 13; j++) {
        float v0 = z[2 * j];
        float v1 = (2 * j + 1 < 25) ? z[2 * j + 1] : 0.f;
        float l0, l1;
        uint32_t hh = bsplit2(v0, v1, l0, l1);
        __nv_bfloat162 ll;
        ll.x = __float2bfloat16_rn(l0); ll.y = __float2bfloat16_rn(l1);
        oh[j] = hh;
        ol[j] = *(uint32_t*)&ll;
    }
}

// ---------------- fused GEMM + mix: out = relu(Amix(W@x) + b + x) ----------------
// grid (16, 2, 64): x = 104-col tile, y = M-tile (o/128), z = n
#define WS_STRIDE 80      // W: 128 o x 32 c bf16 + pad
#define YS_STRIDE 272     // X: 32 c x 104 j bf16 (208B) + 64B pad
#define SM_WH 0
#define SM_WL 10240
#define SM_YH 20480
#define SM_YL 29184
#define STAGE_BYTES 37888
#define SM_TOTAL (2 * STAGE_BYTES)   // 75776
#define ZP_STRIDE 106                 // Z staging stride (floats): conflict-free-ish, even

__global__ void __launch_bounds__(256, 2)
gemm_mix_kernel(const __nv_bfloat16* __restrict__ xhi, const __nv_bfloat16* __restrict__ xlo,
                const __nv_bfloat16* __restrict__ whi, const __nv_bfloat16* __restrict__ wlo,
                const float* __restrict__ b, const float* __restrict__ Amat,
                __nv_bfloat16* __restrict__ outh, __nv_bfloat16* __restrict__ outl,
                float* __restrict__ outf, int last)
{
    extern __shared__ __align__(16) unsigned char smem[];
    const uint32_t smu = smem_u32(smem);

    const int tid  = threadIdx.x;
    const int lane = tid & 31, wid = tid >> 5;
    const int ct   = blockIdx.x;
    const int mt   = blockIdx.y;
    const int n    = blockIdx.z;
    const int col0 = ct * NJ;

    const __nv_bfloat16* Wh = whi + (size_t)(mt * 128) * CC;
    const __nv_bfloat16* Wl = wlo + (size_t)(mt * 128) * CC;
    const __nv_bfloat16* Xh = xhi + ((size_t)n * CC) * TVP + col0;
    const __nv_bfloat16* Xl = xlo + ((size_t)n * CC) * TVP + col0;

    // per-thread cp.async Y indices (c, 8-col group), 416 total = 256 + 160
    const int yc1 = tid / 13,         yg1 = tid % 13;
    const int yq2 = 256 + tid;
    const int yc2 = yq2 / 13,         yg2 = yq2 % 13;
    const bool yv2 = tid < 160;
    // W indices: 512 = 2 x 256
    const int wo1 = tid >> 2,         wg1 = tid & 3;

    auto issue = [&](int kc, int stg) {
        const int c0 = kc * 32;
        const uint32_t sbase = smu + stg * STAGE_BYTES;
        // W: 128 x 32 (2 rounds of 256)
        {
            const size_t src = (size_t)wo1 * CC + c0 + wg1 * 8;
            const uint32_t dst = sbase + wo1 * WS_STRIDE + wg1 * 16;
            cp16(dst + SM_WH, Wh + src);
            cp16(dst + SM_WL, Wl + src);
            const int o2 = wo1 + 64;
            cp16(dst + 64 * WS_STRIDE + SM_WH, Wh + src + (size_t)64 * CC);
            cp16(dst + 64 * WS_STRIDE + SM_WL, Wl + src + (size_t)64 * CC);
        }
        // Y: 32 x 104
        {
            const size_t src1 = (size_t)(c0 + yc1) * TVP + yg1 * 8;
            const uint32_t dst1 = sbase + yc1 * YS_STRIDE + yg1 * 16;
            cp16(dst1 + SM_YH, Xh + src1);
            cp16(dst1 + SM_YL, Xl + src1);
            if (yv2) {
                const size_t src2 = (size_t)(c0 + yc2) * TVP + yg2 * 8;
                const uint32_t dst2 = sbase + yc2 * YS_STRIDE + yg2 * 16;
                cp16(dst2 + SM_YH, Xh + src2);
                cp16(dst2 + SM_YL, Xl + src2);
            }
        }
    };

    float acc[13][4];
#pragma unroll
    for (int nb = 0; nb < 13; nb++)
#pragma unroll
        for (int q = 0; q < 4; q++) acc[nb][q] = 0.f;

    issue(0, 0);
    CP_COMMIT();

    for (int kc = 0; kc < 8; kc++) {
        if (kc < 7) {
            issue(kc + 1, (kc + 1) & 1);
            CP_COMMIT();
            asm volatile("cp.async.wait_group 1;" ::: "memory");
        } else {
            asm volatile("cp.async.wait_group 0;" ::: "memory");
        }
        __syncthreads();

        const uint32_t st  = (kc & 1) ? STAGE_BYTES : 0u;
        const uint32_t swh = smu + st + SM_WH;
        const uint32_t swl = smu + st + SM_WL;
        const uint32_t syh = smu + st + SM_YH;
        const uint32_t syl = smu + st + SM_YL;

#pragma unroll
        for (int s = 0; s < 2; s++) {
            uint32_t Ah[4], Al[4];
            const uint32_t aoff = (uint32_t)(wid * 16 + (lane & 15)) * WS_STRIDE
                                + s * 32 + (lane >> 4) * 16;
            ldsm_x4(Ah, swh + aoff);
            ldsm_x4(Al, swl + aoff);

            const uint32_t boff = (uint32_t)(s * 16 + (lane & 15)) * YS_STRIDE + (lane >> 4) * 16;
#pragma unroll
            for (int g = 0; g < 7; g++) {
                uint32_t Bh[4], Bl[4];
                ldsm_x4_t(Bh, syh + boff + g * 32);
                ldsm_x4_t(Bl, syl + boff + g * 32);
                mma_bf16(acc[2 * g], Ah, &Bh[0]);
                mma_bf16(acc[2 * g], Ah, &Bl[0]);
                mma_bf16(acc[2 * g], Al, &Bh[0]);
                if (g < 6) {
                    mma_bf16(acc[2 * g + 1], Ah, &Bh[2]);
                    mma_bf16(acc[2 * g + 1], Ah, &Bl[2]);
                    mma_bf16(acc[2 * g + 1], Al, &Bh[2]);
                }
            }
        }
        __syncthreads();
    }

    // ---- epilogue: stage Z, load A-pairs, mix, bias+residual+relu, split-store ----
    float* zs  = (float*)smem;                    // [128][ZP_STRIDE]
    ull*   sAp = (ull*)(smem + 128 * ZP_STRIDE * 4);  // 325 u64

    {
        const int g = lane >> 2, tig = lane & 3;
        const int r0 = wid * 16 + g, r1 = r0 + 8;
#pragma unroll
        for (int nb = 0; nb < 13; nb++) {
            const int c = nb * 8 + 2 * tig;
            *(float2*)(zs + r0 * ZP_STRIDE + c) = make_float2(acc[nb][0], acc[nb][1]);
            *(float2*)(zs + r1 * ZP_STRIDE + c) = make_float2(acc[nb][2], acc[nb][3]);
        }
    }
    for (int i = tid; i < 325; i += 256) {
        int u = i / 13, j = i - u * 13;
        float lo = Amat[(2 * j) * VV + u];
        float hi = (2 * j + 1 < VV) ? Amat[(2 * j + 1) * VV + u] : 0.f;
        sAp[i] = pack2f(lo, hi);
    }
    __syncthreads();

    // thread -> (o, t0), rows (o,t0) and (o,t0+1)
    const int o   = tid >> 1;
    const int t0  = 2 * (tid & 1);
    const int oc  = mt * 128 + o;
    const float bias = b[oc];

#pragma unroll
    for (int dt = 0; dt < 2; dt++) {
        const int t  = t0 + dt;
        const int tg = ct * 4 + t;
        const float* z = zs + o * ZP_STRIDE + t * VP2;

        ull macc[13];
#pragma unroll
        for (int j = 0; j < 13; j++) macc[j] = 0ULL;
#pragma unroll
        for (int u = 0; u < 25; u++) {
            ull zu2 = pack2(z[u]);
#pragma unroll
            for (int j = 0; j < 13; j++) macc[j] = ffma2(sAp[u * 13 + j], zu2, macc[j]);
        }

        const size_t rowp = ((size_t)n * CC + oc) * TT + tg;   // padded row index
        const uint32_t* rh = (const uint32_t*)(xhi + rowp * VP2);
        const uint32_t* rl = (const uint32_t*)(xlo + rowp * VP2);

        float vals[26];
#pragma unroll
        for (int j = 0; j < 13; j++) {
            __nv_bfloat162 h2 = *(const __nv_bfloat162*)&rh[j];
            __nv_bfloat162 l2 = *(const __nv_bfloat162*)&rl[j];
            float res0 = __bfloat162float(h2.x) + __bfloat162float(l2.x);
            float res1 = __bfloat162float(h2.y) + __bfloat162float(l2.y);
            vals[2 * j]     = fmaxf(lo32(macc[j]) + bias + res0, 0.f);
            vals[2 * j + 1] = fmaxf(hi32(macc[j]) + bias + res1, 0.f);
        }
        vals[25] = 0.f;

        if (last) {
            float* po = outf + (((size_t)n * CC + oc) * TT + tg) * VV;
#pragma unroll
            for (int v = 0; v < 25; v++) po[v] = vals[v];
        } else {
            uint32_t* oh = (uint32_t*)(outh + rowp * VP2);
            uint32_t* ol = (uint32_t*)(outl + rowp * VP2);
#pragma unroll
            for (int j = 0; j < 13; j++) {
                float l0, l1;
                uint32_t hh = bsplit2(vals[2 * j], vals[2 * j + 1], l0, l1);
                __nv_bfloat162 ll;
                ll.x = __float2bfloat16_rn(l0); ll.y = __float2bfloat16_rn(l1);
                oh[j] = hh;
                ol[j] = *(uint32_t*)&ll;
            }
        }
    }
}

// ---------------- launch ----------------
extern "C" void kernel_launch(void* const* d_in, const int* in_sizes, int n_in,
                              void* d_out, int out_size)
{
    // metadata order: t, x, A, w1, b1, w2, b2, w3, b3, w4, b4
    const float* x  = (const float*)d_in[1];
    const float* A  = (const float*)d_in[2];
    const float* W[4] = { (const float*)d_in[3], (const float*)d_in[5],
                          (const float*)d_in[7], (const float*)d_in[9] };
    const float* B[4] = { (const float*)d_in[4], (const float*)d_in[6],
                          (const float*)d_in[8], (const float*)d_in[10] };
    float* out = (float*)d_out;

    __nv_bfloat16 *xh0, *xl0, *xh1, *xl1, *whi, *wlo;
    cudaGetSymbolAddress((void**)&xh0, g_xh0);
    cudaGetSymbolAddress((void**)&xl0, g_xl0);
    cudaGetSymbolAddress((void**)&xh1, g_xh1);
    cudaGetSymbolAddress((void**)&xl1, g_xl1);
    cudaGetSymbolAddress((void**)&whi, g_whi);
    cudaGetSymbolAddress((void**)&wlo, g_wlo);

    cudaFuncSetAttribute(gemm_mix_kernel,
                         cudaFuncAttributeMaxDynamicSharedMemorySize, SM_TOTAL);

    wsplit_kernel<<<1024, 256>>>(W[0], W[1], W[2], W[3], whi, wlo);
    xsplit_kernel<<<4096, 256>>>(x, xh0, xl0);

    __nv_bfloat16* ih[2] = { xh0, xh1 };
    __nv_bfloat16* il[2] = { xl0, xl1 };
    dim3 ggrid(16, 2, NN);

    for (int l = 0; l < 4; l++) {
        int pi = l & 1, po = 1 - pi;
        gemm_mix_kernel<<<ggrid, 256, SM_TOTAL>>>(
            ih[pi], il[pi], whi + (size_t)l * CC * CC, wlo + (size_t)l * CC * CC,
            B[l], A, ih[po], il[po], out, (l == 3) ? 1 : 0);
    }
}

// round 8
// speedup vs baseline: 1.6745x; 1.6745x over previous
#include <cuda_runtime.h>
#include <cuda_bf16.h>
#include <cstdint>

#define NN 64
#define CC 256
#define TT 64
#define VV 25
#define TV 1600
#define ELEMS (NN * CC * TT * VV)

typedef unsigned long long ull;

// Device scratch (no cudaMalloc allowed)
__device__ float g_r0[ELEMS];                    // residual ping
__device__ float g_r1[ELEMS];                    // residual pong
__device__ __nv_bfloat16 g_yhi[ELEMS];           // mixed tensor, bf16 hi
__device__ __nv_bfloat16 g_ylo[ELEMS];           // mixed tensor, bf16 lo
__device__ __nv_bfloat16 g_whi[4 * CC * CC];     // W hi, all 4 layers
__device__ __nv_bfloat16 g_wlo[4 * CC * CC];     // W lo

// ---------------- PTX helpers ----------------
__device__ __forceinline__ uint32_t smem_u32(const void* p) {
    uint32_t a;
    asm("{ .reg .u64 t; cvta.to.shared.u64 t, %1; cvt.u32.u64 %0, t; }" : "=r"(a) : "l"(p));
    return a;
}
__device__ __forceinline__ ull ffma2(ull a, ull b, ull c) {
    ull d; asm("fma.rn.f32x2 %0, %1, %2, %3;" : "=l"(d) : "l"(a), "l"(b), "l"(c)); return d;
}
__device__ __forceinline__ ull pack2(float x) {
    ull d; unsigned xu = __float_as_uint(x);
    asm("mov.b64 %0, {%1, %2};" : "=l"(d) : "r"(xu), "r"(xu)); return d;
}
__device__ __forceinline__ ull pack2f(float lo, float hi) {
    ull d; asm("mov.b64 %0, {%1, %2};" : "=l"(d) : "r"(__float_as_uint(lo)), "r"(__float_as_uint(hi))); return d;
}
__device__ __forceinline__ float lo32(ull a) { return __uint_as_float((unsigned)(a & 0xffffffffULL)); }
__device__ __forceinline__ float hi32(ull a) { return __uint_as_float((unsigned)(a >> 32)); }

__device__ __forceinline__ void ldsm_x4(uint32_t* r, uint32_t addr) {
    asm volatile("ldmatrix.sync.aligned.m8n8.x4.shared.b16 {%0,%1,%2,%3}, [%4];"
                 : "=r"(r[0]), "=r"(r[1]), "=r"(r[2]), "=r"(r[3]) : "r"(addr));
}
__device__ __forceinline__ void ldsm_x4_t(uint32_t* r, uint32_t addr) {
    asm volatile("ldmatrix.sync.aligned.m8n8.x4.trans.shared.b16 {%0,%1,%2,%3}, [%4];"
                 : "=r"(r[0]), "=r"(r[1]), "=r"(r[2]), "=r"(r[3]) : "r"(addr));
}
__device__ __forceinline__ void mma_bf16(float* c, const uint32_t* a, const uint32_t* b) {
    asm volatile("mma.sync.aligned.m16n8k16.row.col.f32.bf16.bf16.f32 "
                 "{%0,%1,%2,%3}, {%4,%5,%6,%7}, {%8,%9}, {%0,%1,%2,%3};"
                 : "+f"(c[0]), "+f"(c[1]), "+f"(c[2]), "+f"(c[3])
                 : "r"(a[0]), "r"(a[1]), "r"(a[2]), "r"(a[3]), "r"(b[0]), "r"(b[1]));
}
__device__ __forceinline__ void cp16(uint32_t dst, const void* src) {
    asm volatile("cp.async.cg.shared.global [%0], [%1], 16;" :: "r"(dst), "l"(src) : "memory");
}
#define CP_COMMIT() asm volatile("cp.async.commit_group;" ::: "memory")

// ---------------- W split kernel (once, all 4 layers) ----------------
__global__ void __launch_bounds__(256)
wsplit_kernel(const float* __restrict__ w0, const float* __restrict__ w1,
              const float* __restrict__ w2, const float* __restrict__ w3,
              __nv_bfloat16* __restrict__ whi, __nv_bfloat16* __restrict__ wlo)
{
    int id = blockIdx.x * 256 + threadIdx.x;      // 0 .. 262143
    const float* ws[4] = { w0, w1, w2, w3 };
    float v = ws[id >> 16][id & 65535];
    __nv_bfloat16 h = __float2bfloat16_rn(v);
    whi[id] = h;
    wlo[id] = __float2bfloat16_rn(v - __bfloat162float(h));
}

// ---------------- Mix kernel: y = A-mix(x), emitted as bf16 hi/lo ----------------
// 512 threads/CTA, each thread owns one row of 25. Slab = 512 rows = 12800 floats.
// Dynamic smem: slab 12800 floats + 325 ull for packed A (+ pad).
#define MIX_SLAB 12800
#define MIX_SMEM ((MIX_SLAB + 656) * 4)
__global__ void __launch_bounds__(512)
mix_kernel(const float* __restrict__ in, const float* __restrict__ Amat,
           __nv_bfloat16* __restrict__ yhi, __nv_bfloat16* __restrict__ ylo)
{
    extern __shared__ __align__(16) float dsm[];
    float* slab = dsm;
    ull*   sAp  = (ull*)(dsm + MIX_SLAB);

    const int tid = threadIdx.x;
    const size_t base = (size_t)blockIdx.x * MIX_SLAB;

    for (int i = tid; i < 325; i += 512) {
        int u = i / 13, j = i - u * 13;
        float lo = Amat[(2 * j) * VV + u];
        float hi = (2 * j + 1 < VV) ? Amat[(2 * j + 1) * VV + u] : 0.f;
        sAp[i] = pack2f(lo, hi);
    }
    // float4 staging: 3200 float4
    {
        const float4* src = (const float4*)(in + base);
        float4* dst = (float4*)slab;
        for (int i = tid; i < MIX_SLAB / 4; i += 512) dst[i] = src[i];
    }
    __syncthreads();

    const int rb = tid * 25;
    float xr[VV];
#pragma unroll
    for (int u = 0; u < VV; u++) xr[u] = slab[rb + u];

    ull acc[13];
#pragma unroll
    for (int j = 0; j < 13; j++) acc[j] = 0ULL;
#pragma unroll
    for (int u = 0; u < VV; u++) {
        ull xu2 = pack2(xr[u]);
#pragma unroll
        for (int j = 0; j < 13; j++) acc[j] = ffma2(sAp[u * 13 + j], xu2, acc[j]);
    }
#pragma unroll
    for (int j = 0; j < 12; j++) {
        slab[rb + 2 * j]     = lo32(acc[j]);
        slab[rb + 2 * j + 1] = hi32(acc[j]);
    }
    slab[rb + 24] = lo32(acc[12]);
    __syncthreads();

    // emit bf16 hi/lo, coalesced 32-bit stores; float2 slab reads
    uint32_t* yh32 = (uint32_t*)(yhi + base);
    uint32_t* yl32 = (uint32_t*)(ylo + base);
    for (int p = tid; p < MIX_SLAB / 2; p += 512) {
        float2 v = *(const float2*)(slab + 2 * p);
        __nv_bfloat16 h0 = __float2bfloat16_rn(v.x);
        __nv_bfloat16 h1 = __float2bfloat16_rn(v.y);
        __nv_bfloat16 l0 = __float2bfloat16_rn(v.x - __bfloat162float(h0));
        __nv_bfloat16 l1 = __float2bfloat16_rn(v.y - __bfloat162float(h1));
        __nv_bfloat162 hh; hh.x = h0; hh.y = h1;
        __nv_bfloat162 ll; ll.x = l0; ll.y = l1;
        yh32[p] = *(uint32_t*)&hh;
        yl32[p] = *(uint32_t*)&ll;
    }
}

// ---------------- GEMM: out = relu(W @ y + b + xres), 3xBF16 mma.sync ----------------
// grid (13, 2, 64): x = col-tile (128 of 1600), y = M-tile (o/128), z = n
#define WS_STRIDE 80      // 128 rows (o) x 32 c bf16 (64B) + 16B pad
#define YS_STRIDE 272     // 32 rows (c)  x 128 j bf16 (256B) + 16B pad
#define SM_WH 0
#define SM_WL 10240
#define SM_YH 20480
#define SM_YL 29184
#define STAGE_BYTES 37888
#define SM_TOTAL (2 * STAGE_BYTES)   // 75776

__global__ void __launch_bounds__(256, 2)
gemm_kernel(const __nv_bfloat16* __restrict__ yhi, const __nv_bfloat16* __restrict__ ylo,
            const __nv_bfloat16* __restrict__ whi, const __nv_bfloat16* __restrict__ wlo,
            const float* __restrict__ b, const float* __restrict__ xres,
            float* __restrict__ out)
{
    extern __shared__ __align__(16) unsigned char smem[];
    const uint32_t smu = smem_u32(smem);

    const int tid  = threadIdx.x;
    const int lane = tid & 31, wid = tid >> 5;
    const int wm   = wid >> 1, wn = wid & 1;       // warp grid 4 (M) x 2 (N)
    const int ct   = blockIdx.x;
    const int mt   = blockIdx.y;
    const int n    = blockIdx.z;
    const int col0 = ct * 128;

    const __nv_bfloat16* Wh = whi + (size_t)(mt * 128) * CC;
    const __nv_bfloat16* Wl = wlo + (size_t)(mt * 128) * CC;
    const __nv_bfloat16* Yh = yhi + ((size_t)n * CC) * TV + col0;
    const __nv_bfloat16* Yl = ylo + ((size_t)n * CC) * TV + col0;

    // ragged last tile: pre-zero invalid Y region in BOTH stages, skip its cp.asyncs
    if (col0 + 128 > TV) {
        for (int i = tid; i < 1024; i += 256) {
            int stg = i >> 9, hl = (i >> 8) & 1, c = (i >> 3) & 31, jp = 8 + (i & 7);
            uint32_t d = smu + stg * STAGE_BYTES + (hl ? SM_YL : SM_YH)
                       + c * YS_STRIDE + jp * 16;
            asm volatile("st.shared.v4.b32 [%0], {%1,%1,%1,%1};" :: "r"(d), "r"(0) : "memory");
        }
        __syncthreads();
    }

    // issue all cp.asyncs for chunk kc into stage stg (8 x 16B per thread)
    auto issue = [&](int kc, int stg) {
        const int c0 = kc * 32;
        const uint32_t sbase = smu + stg * STAGE_BYTES;
#pragma unroll
        for (int r = 0; r < 2; r++) {
            const int q = tid + r * 256;           // 0..511
            const int o = q >> 2, cp4 = q & 3;
            const size_t wsrc = (size_t)o * CC + c0 + cp4 * 8;
            const uint32_t wdst = sbase + o * WS_STRIDE + cp4 * 16;
            cp16(wdst + SM_WH, Wh + wsrc);
            cp16(wdst + SM_WL, Wl + wsrc);
            const int c = q >> 4, jp = q & 15;
            if (col0 + jp * 8 < TV) {
                const size_t ysrc = (size_t)(c0 + c) * TV + jp * 8;
                const uint32_t ydst = sbase + c * YS_STRIDE + jp * 16;
                cp16(ydst + SM_YH, Yh + ysrc);
                cp16(ydst + SM_YL, Yl + ysrc);
            }
        }
    };

    float acc[2][8][4];
#pragma unroll
    for (int fm = 0; fm < 2; fm++)
#pragma unroll
        for (int nb = 0; nb < 8; nb++)
#pragma unroll
            for (int q = 0; q < 4; q++) acc[fm][nb][q] = 0.f;

    issue(0, 0);
    CP_COMMIT();

    for (int kc = 0; kc < 8; kc++) {
        if (kc < 7) {
            issue(kc + 1, (kc + 1) & 1);
            CP_COMMIT();
            asm volatile("cp.async.wait_group 1;" ::: "memory");
        } else {
            asm volatile("cp.async.wait_group 0;" ::: "memory");
        }
        __syncthreads();

        const uint32_t st  = (kc & 1) ? STAGE_BYTES : 0u;
        const uint32_t swh = smu + st + SM_WH;
        const uint32_t swl = smu + st + SM_WL;
        const uint32_t syh = smu + st + SM_YH;
        const uint32_t syl = smu + st + SM_YL;

#pragma unroll
        for (int s = 0; s < 2; s++) {
            uint32_t Ah[2][4], Al[2][4];
            const uint32_t aoff = (uint32_t)(lane & 15) * WS_STRIDE + s * 32 + (lane >> 4) * 16;
            ldsm_x4(Ah[0], swh + (wm * 32 +  0) * WS_STRIDE + aoff);
            ldsm_x4(Ah[1], swh + (wm * 32 + 16) * WS_STRIDE + aoff);
            ldsm_x4(Al[0], swl + (wm * 32 +  0) * WS_STRIDE + aoff);
            ldsm_x4(Al[1], swl + (wm * 32 + 16) * WS_STRIDE + aoff);

            const uint32_t boff = (uint32_t)(s * 16 + (lane & 15)) * YS_STRIDE + (lane >> 4) * 16;
#pragma unroll
            for (int nbp = 0; nbp < 4; nbp++) {
                uint32_t Bh[4], Bl[4];
                const uint32_t bcol = (uint32_t)(wn * 64 + nbp * 16) * 2;
                ldsm_x4_t(Bh, syh + boff + bcol);
                ldsm_x4_t(Bl, syl + boff + bcol);
#pragma unroll
                for (int h = 0; h < 2; h++) {
                    const int nb = nbp * 2 + h;
                    mma_bf16(acc[0][nb], Ah[0], &Bh[2 * h]);
                    mma_bf16(acc[0][nb], Ah[0], &Bl[2 * h]);
                    mma_bf16(acc[0][nb], Al[0], &Bh[2 * h]);
                    mma_bf16(acc[1][nb], Ah[1], &Bh[2 * h]);
                    mma_bf16(acc[1][nb], Ah[1], &Bl[2 * h]);
                    mma_bf16(acc[1][nb], Al[1], &Bh[2 * h]);
                }
            }
        }
        __syncthreads();
    }

    // ---- epilogue: relu(acc + b[o] + xres) straight to gmem ----
    const int g = lane >> 2, tig = lane & 3;
#pragma unroll
    for (int fm = 0; fm < 2; fm++) {
        const int o0 = mt * 128 + wm * 32 + fm * 16 + g;
        const float bias0 = b[o0];
        const float bias1 = b[o0 + 8];
        const float* r0 = xres + ((size_t)n * CC + o0) * TV;
        const float* r1 = r0 + 8 * TV;
        float* p0 = out + ((size_t)n * CC + o0) * TV;
        float* p1 = p0 + 8 * TV;
#pragma unroll
        for (int nb = 0; nb < 8; nb++) {
            const int j = col0 + wn * 64 + nb * 8 + 2 * tig;
            if (j < TV) {
                float2 ra = *(const float2*)(r0 + j);
                float2 rb = *(const float2*)(r1 + j);
                float2 oa, ob;
                oa.x = fmaxf(acc[fm][nb][0] + bias0 + ra.x, 0.f);
                oa.y = fmaxf(acc[fm][nb][1] + bias0 + ra.y, 0.f);
                ob.x = fmaxf(acc[fm][nb][2] + bias1 + rb.x, 0.f);
                ob.y = fmaxf(acc[fm][nb][3] + bias1 + rb.y, 0.f);
                *(float2*)(p0 + j) = oa;
                *(float2*)(p1 + j) = ob;
            }
        }
    }
}

// ---------------- launch ----------------
extern "C" void kernel_launch(void* const* d_in, const int* in_sizes, int n_in,
                              void* d_out, int out_size)
{
    // metadata order: t, x, A, w1, b1, w2, b2, w3, b3, w4, b4
    const float* x  = (const float*)d_in[1];
    const float* A  = (const float*)d_in[2];
    const float* W[4] = { (const float*)d_in[3], (const float*)d_in[5],
                          (const float*)d_in[7], (const float*)d_in[9] };
    const float* B[4] = { (const float*)d_in[4], (const float*)d_in[6],
                          (const float*)d_in[8], (const float*)d_in[10] };
    float* out = (float*)d_out;

    float *r0, *r1;
    __nv_bfloat16 *yhi, *ylo, *whi, *wlo;
    cudaGetSymbolAddress((void**)&r0,  g_r0);
    cudaGetSymbolAddress((void**)&r1,  g_r1);
    cudaGetSymbolAddress((void**)&yhi, g_yhi);
    cudaGetSymbolAddress((void**)&ylo, g_ylo);
    cudaGetSymbolAddress((void**)&whi, g_whi);
    cudaGetSymbolAddress((void**)&wlo, g_wlo);

    cudaFuncSetAttribute(gemm_kernel,
                         cudaFuncAttributeMaxDynamicSharedMemorySize, SM_TOTAL);
    cudaFuncSetAttribute(mix_kernel,
                         cudaFuncAttributeMaxDynamicSharedMemorySize, MIX_SMEM);

    wsplit_kernel<<<1024, 256>>>(W[0], W[1], W[2], W[3], whi, wlo);

    const float* cur = x;
    float* nxt[4] = { r0, r1, r0, out };
    dim3 ggrid(13, 2, NN);

    for (int l = 0; l < 4; l++) {
        mix_kernel<<<ELEMS / MIX_SLAB, 512, MIX_SMEM>>>(cur, A, yhi, ylo);
        gemm_kernel<<<ggrid, 256, SM_TOTAL>>>(yhi, ylo, whi + l * CC * CC, wlo + l * CC * CC,
                                              B[l], cur, nxt[l]);
        cur = nxt[l];
    }
}